// round 1
// baseline (speedup 1.0000x reference)
#include <cuda_runtime.h>
#include <cuda_bf16.h>
#include <math.h>

// ---------------------------------------------------------------------------
// Problem constants
//   B=16, T=2048, M=4, D=128, F=256, H=4, C=64
//   Nf = B*T = 32768 frames, Nrows = Nf*M = 131072
// ---------------------------------------------------------------------------
#define NFRAMES   32768
#define NROWS     131072
#define DIM_D     128
#define DIM_F     256
#define DIM_QKVS  1024   // q|k|v|s concatenated

// Scratch (device globals: allocation-free, graph-safe)
__device__ float g_h[NROWS * DIM_F];        // 128 MB: hidden activations
__device__ float g_qkvs[NROWS * DIM_QKVS];  // 512 MB: fused q,k,v,s
__device__ float g_wpack[DIM_F * DIM_QKVS]; // 1 MB:   packed [256 x 1024] weights
__device__ float g_bpack[DIM_QKVS];         //         packed bias

// ---------------------------------------------------------------------------
// Pack 4 [256x256] weight matrices (row-major [fi, fo]) into [256 x 1024]
// column blocks: [0,256)=q [256,512)=k [512,768)=v [768,1024)=s
// ---------------------------------------------------------------------------
__global__ void pack_w_kernel(const float* __restrict__ qw, const float* __restrict__ kw,
                              const float* __restrict__ vw, const float* __restrict__ sw,
                              const float* __restrict__ qb, const float* __restrict__ kb,
                              const float* __restrict__ vb, const float* __restrict__ sb)
{
    int idx = blockIdx.x * 256 + threadIdx.x;   // 0 .. 256*1024-1
    int k  = idx >> 10;
    int j  = idx & 1023;
    int sel = j >> 8;
    int jj  = j & 255;
    const float* w = (sel == 0) ? qw : (sel == 1) ? kw : (sel == 2) ? vw : sw;
    g_wpack[idx] = w[k * 256 + jj];
    if (idx < DIM_QKVS) {
        const float* b = (sel == 0) ? qb : (sel == 1) ? kb : (sel == 2) ? vb : sb;
        g_bpack[idx] = b[jj];
    }
}

// ---------------------------------------------------------------------------
// Tiled fp32 GEMM:  C[NROWS x NC] = act(A[NROWS x K] @ W[K x NC] + bias)
// BM=64, BN=64, BK=16, 256 threads, 4x4 microtile per thread.
// K, NC are multiples of 16/64; NROWS multiple of 64. No bounds checks needed.
// ---------------------------------------------------------------------------
#define BM 64
#define BN 64
#define BK 16
#define SPAD 68   // row stride in smem (floats): keeps float4 alignment, spreads banks

__global__ __launch_bounds__(256)
void gemm_bias_act(const float* __restrict__ A, const float* __restrict__ W,
                   const float* __restrict__ bias, float* __restrict__ C,
                   int K, int NC, int relu)
{
    __shared__ __align__(16) float As[BK][SPAD];
    __shared__ __align__(16) float Ws[BK][SPAD];

    const int tid = threadIdx.x;
    const int tx = tid & 15;          // 0..15 -> 4 columns each
    const int ty = tid >> 4;          // 0..15 -> 4 rows each
    const int row0 = blockIdx.y * BM;
    const int col0 = blockIdx.x * BN;

    float acc[4][4];
#pragma unroll
    for (int i = 0; i < 4; i++)
#pragma unroll
        for (int j = 0; j < 4; j++) acc[i][j] = 0.f;

    for (int k0 = 0; k0 < K; k0 += BK) {
        // Load A tile [64 rows x 16 k] -> As[k][m] (transposed), coalesced 16-wide
#pragma unroll
        for (int r = 0; r < 4; r++) {
            int idx = tid + r * 256;          // 0..1023
            int kk = idx & 15;
            int m  = idx >> 4;
            As[kk][m] = A[(size_t)(row0 + m) * K + (k0 + kk)];
        }
        // Load W tile [16 k x 64 n] -> Ws[k][n], coalesced 64-wide
#pragma unroll
        for (int r = 0; r < 4; r++) {
            int idx = tid + r * 256;
            int n  = idx & 63;
            int kk = idx >> 6;
            Ws[kk][n] = W[(size_t)(k0 + kk) * NC + (col0 + n)];
        }
        __syncthreads();

#pragma unroll
        for (int kk = 0; kk < BK; kk++) {
            float4 av = *reinterpret_cast<const float4*>(&As[kk][ty * 4]);
            float4 bv = *reinterpret_cast<const float4*>(&Ws[kk][tx * 4]);
            float a[4] = {av.x, av.y, av.z, av.w};
            float b[4] = {bv.x, bv.y, bv.z, bv.w};
#pragma unroll
            for (int i = 0; i < 4; i++)
#pragma unroll
                for (int j = 0; j < 4; j++) acc[i][j] = fmaf(a[i], b[j], acc[i][j]);
        }
        __syncthreads();
    }

    // Epilogue: bias (+relu), vectorized store
    const int col = col0 + tx * 4;
    float4 b4 = *reinterpret_cast<const float4*>(&bias[col]);
#pragma unroll
    for (int i = 0; i < 4; i++) {
        int row = row0 + ty * 4 + i;
        float4 c4;
        c4.x = acc[i][0] + b4.x;
        c4.y = acc[i][1] + b4.y;
        c4.z = acc[i][2] + b4.z;
        c4.w = acc[i][3] + b4.w;
        if (relu) {
            c4.x = fmaxf(c4.x, 0.f); c4.y = fmaxf(c4.y, 0.f);
            c4.z = fmaxf(c4.z, 0.f); c4.w = fmaxf(c4.w, 0.f);
        }
        *reinterpret_cast<float4*>(&C[(size_t)row * NC + col]) = c4;
    }
}

// ---------------------------------------------------------------------------
// Fused per-frame: attention (M=4, H=4, C=64, no self edges) + beta-gated skip
//                  + LayerNorm + ReLU
// One block (256 threads) per frame. Thread t owns feature t for all 4 nodes.
// ---------------------------------------------------------------------------
__global__ __launch_bounds__(256)
void attn_ln_kernel(const float* __restrict__ qkvs,   // [NROWS x 1024]
                    const float* __restrict__ bw,     // [768]
                    const float* __restrict__ ln_g,   // [256]
                    const float* __restrict__ ln_b,   // [256]
                    float* __restrict__ out)          // [NROWS x 256]
{
    __shared__ float s_all[4 * DIM_QKVS];   // 16 KB: per-node q|k|v|s
    __shared__ float s_sc[64];
    __shared__ float s_alpha[64];
    __shared__ float s_red[8 * 256];        // 8 KB reduction workspace

    const int frame = blockIdx.x;
    const int tid = threadIdx.x;
    const float* src = qkvs + (size_t)frame * (4 * DIM_QKVS);

#pragma unroll
    for (int r = 0; r < 16; r++) s_all[tid + r * 256] = src[tid + r * 256];
    __syncthreads();

    // scores[h][i][j] = (q_i . k_j)/8, j != i
    if (tid < 64) {
        int h = tid >> 4, i = (tid >> 2) & 3, j = tid & 3;
        float d = -1e30f;
        if (i != j) {
            const float* qp = &s_all[i * 1024 + h * 64];
            const float* kp = &s_all[j * 1024 + 256 + h * 64];
            float acc = 0.f;
#pragma unroll
            for (int c = 0; c < 64; c++) acc = fmaf(qp[c], kp[c], acc);
            d = acc * 0.125f;   // 1/sqrt(64)
        }
        s_sc[tid] = d;
    }
    __syncthreads();

    // masked softmax over j != i
    if (tid < 16) {
        int h = tid >> 2, i = tid & 3;
        int base = h * 16 + i * 4;
        float m = -1e30f;
#pragma unroll
        for (int j = 0; j < 4; j++) if (j != i) m = fmaxf(m, s_sc[base + j]);
        float e[4]; float sum = 0.f;
#pragma unroll
        for (int j = 0; j < 4; j++) {
            e[j] = (j == i) ? 0.f : expf(s_sc[base + j] - m);
            sum += e[j];
        }
        float inv = 1.f / sum;
#pragma unroll
        for (int j = 0; j < 4; j++) s_alpha[base + j] = e[j] * inv;
    }
    __syncthreads();

    // out_i[f] = sum_j alpha[h][i][j] * v_j[f]   (alpha_ii = 0)
    const int h = tid >> 6;
    float o[4], xr[4];
#pragma unroll
    for (int i = 0; i < 4; i++) {
        float acc = 0.f;
#pragma unroll
        for (int j = 0; j < 4; j++)
            acc = fmaf(s_alpha[h * 16 + i * 4 + j], s_all[j * 1024 + 512 + tid], acc);
        o[i]  = acc;
        xr[i] = s_all[i * 1024 + 768 + tid];   // skip branch x_r = s
    }

    // beta_i = sigmoid( [out, x_r, out-x_r] . bw ) : per-node block reduction
    float bw0 = __ldg(&bw[tid]), bw1 = __ldg(&bw[256 + tid]), bw2 = __ldg(&bw[512 + tid]);
#pragma unroll
    for (int i = 0; i < 4; i++)
        s_red[i * 256 + tid] = o[i] * bw0 + xr[i] * bw1 + (o[i] - xr[i]) * bw2;
    __syncthreads();
    for (int s = 128; s > 0; s >>= 1) {
        if (tid < s) {
#pragma unroll
            for (int i = 0; i < 4; i++) s_red[i * 256 + tid] += s_red[i * 256 + tid + s];
        }
        __syncthreads();
    }
    float y[4];
#pragma unroll
    for (int i = 0; i < 4; i++) {
        float beta = 1.f / (1.f + expf(-s_red[i * 256]));
        y[i] = beta * xr[i] + (1.f - beta) * o[i];
    }
    __syncthreads();   // done reading beta sums before reuse of s_red

    // LayerNorm stats: sum and sum of squares per node
#pragma unroll
    for (int i = 0; i < 4; i++) {
        s_red[i * 256 + tid]       = y[i];
        s_red[(4 + i) * 256 + tid] = y[i] * y[i];
    }
    __syncthreads();
    for (int s = 128; s > 0; s >>= 1) {
        if (tid < s) {
#pragma unroll
            for (int i = 0; i < 8; i++) s_red[i * 256 + tid] += s_red[i * 256 + tid + s];
        }
        __syncthreads();
    }

    const float g = __ldg(&ln_g[tid]);
    const float b = __ldg(&ln_b[tid]);
    float* dst = out + (size_t)frame * (4 * DIM_F);
#pragma unroll
    for (int i = 0; i < 4; i++) {
        float mu  = s_red[i * 256] * (1.f / 256.f);
        float ex2 = s_red[(4 + i) * 256] * (1.f / 256.f);
        float var = ex2 - mu * mu;
        float inv = rsqrtf(var + 1e-5f);
        float val = (y[i] - mu) * inv * g + b;
        dst[i * 256 + tid] = fmaxf(val, 0.f);
    }
}

// ---------------------------------------------------------------------------
// Launch: emb GEMM+ReLU -> [pack, QKVS GEMM, attn+LN] x2
// ---------------------------------------------------------------------------
extern "C" void kernel_launch(void* const* d_in, const int* in_sizes, int n_in,
                              void* d_out, int out_size)
{
    (void)in_sizes; (void)n_in; (void)out_size;
    const float* x     = (const float*)d_in[0];
    const float* emb_w = (const float*)d_in[1];
    const float* emb_b = (const float*)d_in[2];
    const float* q1w = (const float*)d_in[3];  const float* q1b = (const float*)d_in[4];
    const float* k1w = (const float*)d_in[5];  const float* k1b = (const float*)d_in[6];
    const float* v1w = (const float*)d_in[7];  const float* v1b = (const float*)d_in[8];
    const float* s1w = (const float*)d_in[9];  const float* s1b = (const float*)d_in[10];
    const float* b1w = (const float*)d_in[11];
    const float* ln1_g = (const float*)d_in[12]; const float* ln1_b = (const float*)d_in[13];
    const float* q2w = (const float*)d_in[14]; const float* q2b = (const float*)d_in[15];
    const float* k2w = (const float*)d_in[16]; const float* k2b = (const float*)d_in[17];
    const float* v2w = (const float*)d_in[18]; const float* v2b = (const float*)d_in[19];
    const float* s2w = (const float*)d_in[20]; const float* s2b = (const float*)d_in[21];
    const float* b2w = (const float*)d_in[22];
    const float* ln2_g = (const float*)d_in[23]; const float* ln2_b = (const float*)d_in[24];
    float* out = (float*)d_out;

    float *h, *qkvs, *wp, *bp;
    cudaGetSymbolAddress((void**)&h, g_h);
    cudaGetSymbolAddress((void**)&qkvs, g_qkvs);
    cudaGetSymbolAddress((void**)&wp, g_wpack);
    cudaGetSymbolAddress((void**)&bp, g_bpack);

    // Embedding: h = relu(x @ emb_w + emb_b)
    gemm_bias_act<<<dim3(DIM_F / BN, NROWS / BM), 256>>>(x, emb_w, emb_b, h, DIM_D, DIM_F, 1);

    // --- Conv 1 ---
    pack_w_kernel<<<(DIM_F * DIM_QKVS) / 256, 256>>>(q1w, k1w, v1w, s1w, q1b, k1b, v1b, s1b);
    gemm_bias_act<<<dim3(DIM_QKVS / BN, NROWS / BM), 256>>>(h, wp, bp, qkvs, DIM_F, DIM_QKVS, 0);
    attn_ln_kernel<<<NFRAMES, 256>>>(qkvs, b1w, ln1_g, ln1_b, h);

    // --- Conv 2 ---
    pack_w_kernel<<<(DIM_F * DIM_QKVS) / 256, 256>>>(q2w, k2w, v2w, s2w, q2b, k2b, v2b, s2b);
    gemm_bias_act<<<dim3(DIM_QKVS / BN, NROWS / BM), 256>>>(h, wp, bp, qkvs, DIM_F, DIM_QKVS, 0);
    attn_ln_kernel<<<NFRAMES, 256>>>(qkvs, b2w, ln2_g, ln2_b, out);
}

// round 2
// speedup vs baseline: 2.6833x; 2.6833x over previous
#include <cuda_runtime.h>
#include <math.h>

// ---------------------------------------------------------------------------
// B=16, T=2048, M=4, D=128, F=256, H=4, C=64
// Nf = 32768 frames, Nrows = 131072
// ---------------------------------------------------------------------------
#define NFRAMES   32768
#define NROWS     131072
#define DIM_D     128
#define DIM_F     256
#define DIM_QKVS  1024

// Scratch (device globals: allocation-free, graph-safe)
__device__ float g_h[NROWS * DIM_F];          // hidden activations
__device__ float g_qkvs[NROWS * DIM_QKVS];    // fused q|k|v|s
__device__ float g_wT[DIM_QKVS * DIM_F];      // transposed packed weights [NC][K]
__device__ float g_bpack[DIM_QKVS];           // packed bias

// ---------------------------------------------------------------------------
// Transpose-pack one [K x 256] weight matrix into g_wT[(n_off+n)*K + k].
// ---------------------------------------------------------------------------
__global__ void pack_T(const float* __restrict__ w, const float* __restrict__ b,
                       int K, int n_off)
{
    int idx = blockIdx.x * 256 + threadIdx.x;   // K*256 total
    int k = idx >> 8;
    int n = idx & 255;
    g_wT[(size_t)(n_off + n) * K + k] = w[k * 256 + n];
    if (idx < 256) g_bpack[n_off + idx] = b[idx];
}

// ---------------------------------------------------------------------------
// TF32 tensor-core GEMM: C[NROWS x NC] = act(A[NROWS x K] @ W[K x NC] + bias)
// W supplied transposed as Wt[NC x K]. BM=BN=128, BK=32, 256 threads (8 warps,
// 4x2), warp tile 32x64 via mma.sync.m16n8k8 tf32. ldmatrix for A and B from
// XOR-swizzled smem.
// ---------------------------------------------------------------------------
__device__ __forceinline__ unsigned f2tf(float x) {
    unsigned u;
    asm("cvt.rna.tf32.f32 %0, %1;" : "=r"(u) : "f"(x));
    return u;
}

#define LDSM_X4(r, addr)                                                        \
    asm volatile("ldmatrix.sync.aligned.m8n8.x4.shared.b16 {%0,%1,%2,%3}, [%4];" \
                 : "=r"((r)[0]), "=r"((r)[1]), "=r"((r)[2]), "=r"((r)[3])        \
                 : "r"(addr))

#define MMA_TF32(c, a, b0v, b1v)                                                \
    asm volatile("mma.sync.aligned.m16n8k8.row.col.f32.tf32.tf32.f32 "          \
                 "{%0,%1,%2,%3},{%4,%5,%6,%7},{%8,%9},{%0,%1,%2,%3};"           \
                 : "+f"((c)[0]), "+f"((c)[1]), "+f"((c)[2]), "+f"((c)[3])        \
                 : "r"((a)[0]), "r"((a)[1]), "r"((a)[2]), "r"((a)[3]),           \
                   "r"(b0v), "r"(b1v))

__global__ __launch_bounds__(256, 2)
void gemm_tf32(const float* __restrict__ A, const float* __restrict__ Wt,
               const float* __restrict__ bias, float* __restrict__ C,
               int K, int NC, int relu)
{
    __shared__ __align__(16) unsigned As[128 * 32];
    __shared__ __align__(16) unsigned Bs[128 * 32];

    const int tid  = threadIdx.x;
    const int lane = tid & 31;
    const int wid  = tid >> 5;
    const int wm   = wid >> 1;     // 0..3
    const int wn   = wid & 1;      // 0..1
    const int row0 = blockIdx.y * 128;
    const int col0 = blockIdx.x * 128;

    float acc[2][8][4];
#pragma unroll
    for (int mi = 0; mi < 2; mi++)
#pragma unroll
        for (int nf = 0; nf < 8; nf++)
#pragma unroll
            for (int c = 0; c < 4; c++) acc[mi][nf][c] = 0.f;

    // ldmatrix lane bases (row within smem tile, chunk high bit)
    const int arow = wm * 32 + (lane & 7) + ((lane >> 3) & 1) * 8;   // + mi*16
    const int ahc  = lane >> 4;                                      // 0/1
    const int brow = wn * 64 + (lane & 7) + ((lane >> 4) & 1) * 8;   // + p*16
    const int bhc  = (lane >> 3) & 1;

    const unsigned asb = (unsigned)__cvta_generic_to_shared(As);
    const unsigned bsb = (unsigned)__cvta_generic_to_shared(Bs);

    for (int k0 = 0; k0 < K; k0 += 32) {
        // ---- stage A and B tiles (convert to tf32, XOR-chunk swizzle) ----
#pragma unroll
        for (int r = 0; r < 4; r++) {
            int idx = tid + r * 256;       // 0..1023
            int rr  = idx >> 3;            // row 0..127
            int c   = idx & 7;             // 16B chunk 0..7
            int sc  = (c ^ (rr & 7)) << 2; // swizzled float offset

            float4 va = *(const float4*)&A[(size_t)(row0 + rr) * K + k0 + c * 4];
            uint4 ua = make_uint4(f2tf(va.x), f2tf(va.y), f2tf(va.z), f2tf(va.w));
            *(uint4*)&As[rr * 32 + sc] = ua;

            float4 vb = *(const float4*)&Wt[(size_t)(col0 + rr) * K + k0 + c * 4];
            uint4 ub = make_uint4(f2tf(vb.x), f2tf(vb.y), f2tf(vb.z), f2tf(vb.w));
            *(uint4*)&Bs[rr * 32 + sc] = ub;
        }
        __syncthreads();

        // ---- 4 k-steps of 8 ----
#pragma unroll
        for (int s = 0; s < 4; s++) {
            unsigned a[2][4];
#pragma unroll
            for (int mi = 0; mi < 2; mi++) {
                int row = arow + mi * 16;
                int ch  = (s * 2 + ahc) ^ (row & 7);
                unsigned addr = asb + (unsigned)((row * 32 + ch * 4) * 4);
                LDSM_X4(a[mi], addr);
            }
            unsigned b[4][4];   // [p]: {b0 nf=2p, b1 nf=2p, b0 nf=2p+1, b1 nf=2p+1}
#pragma unroll
            for (int p = 0; p < 4; p++) {
                int row = brow + p * 16;
                int ch  = (s * 2 + bhc) ^ (row & 7);
                unsigned addr = bsb + (unsigned)((row * 32 + ch * 4) * 4);
                LDSM_X4(b[p], addr);
            }
#pragma unroll
            for (int mi = 0; mi < 2; mi++)
#pragma unroll
                for (int nf = 0; nf < 8; nf++)
                    MMA_TF32(acc[mi][nf], a[mi],
                             b[nf >> 1][(nf & 1) * 2], b[nf >> 1][(nf & 1) * 2 + 1]);
        }
        __syncthreads();
    }

    // ---- epilogue: bias (+relu), float2 stores ----
    const int g = lane >> 2, t = lane & 3;
#pragma unroll
    for (int mi = 0; mi < 2; mi++) {
        int row = row0 + wm * 32 + mi * 16 + g;
#pragma unroll
        for (int nf = 0; nf < 8; nf++) {
            int col = col0 + wn * 64 + nf * 8 + t * 2;
            float2 bb = *(const float2*)&bias[col];
            float2 v0 = make_float2(acc[mi][nf][0] + bb.x, acc[mi][nf][1] + bb.y);
            float2 v1 = make_float2(acc[mi][nf][2] + bb.x, acc[mi][nf][3] + bb.y);
            if (relu) {
                v0.x = fmaxf(v0.x, 0.f); v0.y = fmaxf(v0.y, 0.f);
                v1.x = fmaxf(v1.x, 0.f); v1.y = fmaxf(v1.y, 0.f);
            }
            *(float2*)&C[(size_t)row * NC + col]       = v0;
            *(float2*)&C[(size_t)(row + 8) * NC + col] = v1;
        }
    }
}

// ---------------------------------------------------------------------------
// Fused per-frame: attention (M=4,H=4,C=64, no self edges) + beta skip + LN +
// ReLU. One block (256 thr) per frame; warp-shuffle reductions.
// ---------------------------------------------------------------------------
__device__ __forceinline__ float warp_sum(float v) {
#pragma unroll
    for (int o = 16; o > 0; o >>= 1) v += __shfl_xor_sync(0xffffffffu, v, o);
    return v;
}

__global__ __launch_bounds__(256)
void attn_ln_kernel(const float* __restrict__ qkvs,   // [NROWS x 1024]
                    const float* __restrict__ bw,     // [768]
                    const float* __restrict__ ln_g,   // [256]
                    const float* __restrict__ ln_b,   // [256]
                    float* __restrict__ out)          // [NROWS x 256]
{
    __shared__ __align__(16) float s_all[4 * DIM_QKVS];   // 16 KB
    __shared__ float s_sc[64];
    __shared__ float s_alpha[64];
    __shared__ float s_part[64];

    const int frame = blockIdx.x;
    const int tid   = threadIdx.x;
    const int lane  = tid & 31;
    const int wid   = tid >> 5;

    const float4* src = (const float4*)(qkvs + (size_t)frame * (4 * DIM_QKVS));
    float4* dst4 = (float4*)s_all;
#pragma unroll
    for (int r = 0; r < 4; r++) dst4[tid + r * 256] = src[tid + r * 256];
    __syncthreads();

    // scores[h][i][j] = (q_i . k_j)/8
    if (tid < 64) {
        int h = tid >> 4, i = (tid >> 2) & 3, j = tid & 3;
        float d = -1e30f;
        if (i != j) {
            const float4* qp = (const float4*)&s_all[i * 1024 + h * 64];
            const float4* kp = (const float4*)&s_all[j * 1024 + 256 + h * 64];
            float acc = 0.f;
#pragma unroll
            for (int c = 0; c < 16; c++) {
                float4 a = qp[c], b = kp[c];
                acc += a.x * b.x + a.y * b.y + a.z * b.z + a.w * b.w;
            }
            d = acc * 0.125f;
        }
        s_sc[tid] = d;
    }
    __syncthreads();

    // masked softmax over j != i
    if (tid < 16) {
        int h = tid >> 2, i = tid & 3;
        int base = h * 16 + i * 4;
        float m = -1e30f;
#pragma unroll
        for (int j = 0; j < 4; j++) if (j != i) m = fmaxf(m, s_sc[base + j]);
        float e[4]; float sum = 0.f;
#pragma unroll
        for (int j = 0; j < 4; j++) {
            e[j] = (j == i) ? 0.f : expf(s_sc[base + j] - m);
            sum += e[j];
        }
        float inv = 1.f / sum;
#pragma unroll
        for (int j = 0; j < 4; j++) s_alpha[base + j] = e[j] * inv;
    }
    __syncthreads();

    // out_i[f] = sum_j alpha[h][i][j] * v_j[f]
    const int h = tid >> 6;
    float o[4], xr[4];
#pragma unroll
    for (int i = 0; i < 4; i++) {
        float acc = 0.f;
#pragma unroll
        for (int j = 0; j < 4; j++)
            acc = fmaf(s_alpha[h * 16 + i * 4 + j], s_all[j * 1024 + 512 + tid], acc);
        o[i]  = acc;
        xr[i] = s_all[i * 1024 + 768 + tid];
    }

    // beta_i = sigmoid([out, x_r, out-x_r] . bw): shuffle + 8-partial reduce
    const float bw0 = __ldg(&bw[tid]);
    const float bw1 = __ldg(&bw[256 + tid]);
    const float bw2 = __ldg(&bw[512 + tid]);
#pragma unroll
    for (int i = 0; i < 4; i++) {
        float v = warp_sum(o[i] * bw0 + xr[i] * bw1 + (o[i] - xr[i]) * bw2);
        if (lane == 0) s_part[i * 8 + wid] = v;
    }
    __syncthreads();

    float y[4];
#pragma unroll
    for (int i = 0; i < 4; i++) {
        float s = 0.f;
#pragma unroll
        for (int w = 0; w < 8; w++) s += s_part[i * 8 + w];
        float beta = 1.f / (1.f + expf(-s));
        y[i] = beta * xr[i] + (1.f - beta) * o[i];
    }
    __syncthreads();   // all reads of s_part done before reuse

    // LayerNorm stats: sum and sumsq per node
#pragma unroll
    for (int i = 0; i < 4; i++) {
        float vs = warp_sum(y[i]);
        float vq = warp_sum(y[i] * y[i]);
        if (lane == 0) { s_part[i * 8 + wid] = vs; s_part[32 + i * 8 + wid] = vq; }
    }
    __syncthreads();

    const float g = __ldg(&ln_g[tid]);
    const float b = __ldg(&ln_b[tid]);
    float* dst = out + (size_t)frame * (4 * DIM_F);
#pragma unroll
    for (int i = 0; i < 4; i++) {
        float ssum = 0.f, ssq = 0.f;
#pragma unroll
        for (int w = 0; w < 8; w++) { ssum += s_part[i * 8 + w]; ssq += s_part[32 + i * 8 + w]; }
        float mu  = ssum * (1.f / 256.f);
        float var = ssq * (1.f / 256.f) - mu * mu;
        float inv = rsqrtf(var + 1e-5f);
        float val = (y[i] - mu) * inv * g + b;
        dst[i * 256 + tid] = fmaxf(val, 0.f);
    }
}

// ---------------------------------------------------------------------------
// Launch sequence
// ---------------------------------------------------------------------------
extern "C" void kernel_launch(void* const* d_in, const int* in_sizes, int n_in,
                              void* d_out, int out_size)
{
    (void)in_sizes; (void)n_in; (void)out_size;
    const float* x     = (const float*)d_in[0];
    const float* emb_w = (const float*)d_in[1];
    const float* emb_b = (const float*)d_in[2];
    const float* q1w = (const float*)d_in[3];  const float* q1b = (const float*)d_in[4];
    const float* k1w = (const float*)d_in[5];  const float* k1b = (const float*)d_in[6];
    const float* v1w = (const float*)d_in[7];  const float* v1b = (const float*)d_in[8];
    const float* s1w = (const float*)d_in[9];  const float* s1b = (const float*)d_in[10];
    const float* b1w = (const float*)d_in[11];
    const float* ln1_g = (const float*)d_in[12]; const float* ln1_b = (const float*)d_in[13];
    const float* q2w = (const float*)d_in[14]; const float* q2b = (const float*)d_in[15];
    const float* k2w = (const float*)d_in[16]; const float* k2b = (const float*)d_in[17];
    const float* v2w = (const float*)d_in[18]; const float* v2b = (const float*)d_in[19];
    const float* s2w = (const float*)d_in[20]; const float* s2b = (const float*)d_in[21];
    const float* b2w = (const float*)d_in[22];
    const float* ln2_g = (const float*)d_in[23]; const float* ln2_b = (const float*)d_in[24];
    float* out = (float*)d_out;

    float *h, *qkvs, *wp, *bp;
    cudaGetSymbolAddress((void**)&h, g_h);
    cudaGetSymbolAddress((void**)&qkvs, g_qkvs);
    cudaGetSymbolAddress((void**)&wp, g_wT);
    cudaGetSymbolAddress((void**)&bp, g_bpack);

    // Embedding: h = relu(x @ emb_w + emb_b)
    pack_T<<<DIM_D, 256>>>(emb_w, emb_b, DIM_D, 0);
    gemm_tf32<<<dim3(DIM_F / 128, NROWS / 128), 256>>>(x, wp, bp, h, DIM_D, DIM_F, 1);

    // --- Conv 1 ---
    pack_T<<<DIM_F, 256>>>(q1w, q1b, DIM_F, 0);
    pack_T<<<DIM_F, 256>>>(k1w, k1b, DIM_F, 256);
    pack_T<<<DIM_F, 256>>>(v1w, v1b, DIM_F, 512);
    pack_T<<<DIM_F, 256>>>(s1w, s1b, DIM_F, 768);
    gemm_tf32<<<dim3(DIM_QKVS / 128, NROWS / 128), 256>>>(h, wp, bp, qkvs, DIM_F, DIM_QKVS, 0);
    attn_ln_kernel<<<NFRAMES, 256>>>(qkvs, b1w, ln1_g, ln1_b, h);

    // --- Conv 2 ---
    pack_T<<<DIM_F, 256>>>(q2w, q2b, DIM_F, 0);
    pack_T<<<DIM_F, 256>>>(k2w, k2b, DIM_F, 256);
    pack_T<<<DIM_F, 256>>>(v2w, v2b, DIM_F, 512);
    pack_T<<<DIM_F, 256>>>(s2w, s2b, DIM_F, 768);
    gemm_tf32<<<dim3(DIM_QKVS / 128, NROWS / 128), 256>>>(h, wp, bp, qkvs, DIM_F, DIM_QKVS, 0);
    attn_ln_kernel<<<NFRAMES, 256>>>(qkvs, b2w, ln2_g, ln2_b, out);
}

// round 4
// speedup vs baseline: 2.9976x; 1.1171x over previous
#include <cuda_runtime.h>
#include <cstdint>
#include <math.h>

// ---------------------------------------------------------------------------
// B=16, T=2048, M=4, D=128, F=256, H=4, C=64
// Nf = 32768 frames, Nrows = 131072
// NOTE: bench toolchain targets sm_100 (no 'a' features) -> legacy mma.sync
// ---------------------------------------------------------------------------
#define NFRAMES   32768
#define NROWS     131072
#define DIM_D     128
#define DIM_F     256
#define DIM_QKVS  1024

// Scratch (device globals: allocation-free, graph-safe)
__device__ float g_h[NROWS * DIM_F];          // hidden activations (tf32-rounded)
__device__ float g_qkvs[NROWS * DIM_QKVS];    // fused q|k|v|s (also holds rounded x)
__device__ float g_wT[DIM_QKVS * DIM_F];      // transposed packed weights [NC][K]
__device__ float g_bpack[DIM_QKVS];           // packed bias

__device__ __forceinline__ unsigned f2tf(float x) {
    unsigned u;
    asm("cvt.rna.tf32.f32 %0, %1;" : "=r"(u) : "f"(x));
    return u;
}
__device__ __forceinline__ float f2tff(float x) { return __uint_as_float(f2tf(x)); }

__device__ __forceinline__ uint32_t swz(uint32_t off) {   // 128B-row XOR swizzle
    return off ^ ((off >> 3) & 0x70);
}

#define CP_ASYNC16(dst, src) \
    asm volatile("cp.async.cg.shared.global [%0], [%1], 16;" :: "r"(dst), "l"(src))
#define CP_COMMIT() asm volatile("cp.async.commit_group;")
#define CP_WAIT1()  asm volatile("cp.async.wait_group 1;" ::: "memory")
#define CP_WAIT0()  asm volatile("cp.async.wait_group 0;" ::: "memory")

#define LDSM_X4(r, addr)                                                        \
    asm volatile("ldmatrix.sync.aligned.m8n8.x4.shared.b16 {%0,%1,%2,%3}, [%4];" \
                 : "=r"((r)[0]), "=r"((r)[1]), "=r"((r)[2]), "=r"((r)[3])        \
                 : "r"(addr))

#define MMA_TF32(c, a, b0v, b1v)                                                \
    asm volatile("mma.sync.aligned.m16n8k8.row.col.f32.tf32.tf32.f32 "          \
                 "{%0,%1,%2,%3},{%4,%5,%6,%7},{%8,%9},{%0,%1,%2,%3};"           \
                 : "+f"((c)[0]), "+f"((c)[1]), "+f"((c)[2]), "+f"((c)[3])        \
                 : "r"((a)[0]), "r"((a)[1]), "r"((a)[2]), "r"((a)[3]),           \
                   "r"(b0v), "r"(b1v))

// ---------------------------------------------------------------------------
// tf32 mma.sync GEMM, cp.async 3-stage pipeline.
// C[NROWS x NC] = act(A @ Wt^T + bias);  A pre-rounded to tf32, Wt [NC x K]
// pre-rounded. BM=128, BN=256, BK=32, 512 threads (16 warps 4x4, 32x64 warp
// tile). flags: bit0 = relu, bit1 = round output to tf32.
// ---------------------------------------------------------------------------
#define STAGES 3
#define ASZ (128 * 32 * 4)   // 16 KB
#define BSZ (256 * 32 * 4)   // 32 KB
#define GEMM_SMEM (STAGES * (ASZ + BSZ))   // 147456 B

__global__ __launch_bounds__(512, 1)
void gemm_tf32(const float* __restrict__ A, const float* __restrict__ Wt,
               const float* __restrict__ bias, float* __restrict__ C,
               int K, int NC, int flags)
{
    extern __shared__ __align__(128) char smem[];
    const uint32_t smem_u = (uint32_t)__cvta_generic_to_shared(smem);
    const uint32_t a_u = smem_u;
    const uint32_t b_u = smem_u + STAGES * ASZ;

    const int tid  = threadIdx.x;
    const int lane = tid & 31;
    const int wid  = tid >> 5;
    const int wm   = wid & 3;      // 0..3 row groups (32 rows)
    const int wn   = wid >> 2;     // 0..3 col groups (64 cols)
    const int row0 = blockIdx.y * 128;
    const int col0 = blockIdx.x * 256;

    float acc[2][8][4];
#pragma unroll
    for (int mi = 0; mi < 2; mi++)
#pragma unroll
        for (int nf = 0; nf < 8; nf++)
#pragma unroll
            for (int c = 0; c < 4; c++) acc[mi][nf][c] = 0.f;

    const int nch = K >> 5;

    // per-thread staging indices
    // A: 1024 16B-chunks (128 rows x 8), 2 per thread
    // B: 2048 16B-chunks (256 rows x 8), 4 per thread
    const int ar[2] = { tid >> 3, (tid + 512) >> 3 };
    const int ac    = tid & 7;
    const int br[4] = { tid >> 3, (tid + 512) >> 3, (tid + 1024) >> 3, (tid + 1536) >> 3 };

    auto stage = [&](int s, int c) {
        const int k0 = c * 32;
        const uint32_t abase = a_u + s * ASZ;
        const uint32_t bbase = b_u + s * BSZ;
#pragma unroll
        for (int t = 0; t < 2; t++) {
            const float* src = A + (size_t)(row0 + ar[t]) * K + k0 + ac * 4;
            CP_ASYNC16(abase + swz(ar[t] * 128 + ac * 16), src);
        }
#pragma unroll
        for (int t = 0; t < 4; t++) {
            const float* src = Wt + (size_t)(col0 + br[t]) * K + k0 + ac * 4;
            CP_ASYNC16(bbase + swz(br[t] * 128 + ac * 16), src);
        }
    };

    stage(0, 0); CP_COMMIT();
    stage(1, 1); CP_COMMIT();

    // ldmatrix lane bases
    const int arow0 = wm * 32 + (lane & 7) + ((lane >> 3) & 1) * 8;
    const int ahc   = lane >> 4;
    const int brow0 = wn * 64 + (lane & 7) + ((lane >> 4) & 1) * 8;
    const int bhc   = (lane >> 3) & 1;

    for (int c = 0; c < nch; c++) {
        CP_WAIT1();
        __syncthreads();
        const int s = c % STAGES;
        if (c + 2 < nch) stage((c + 2) % STAGES, c + 2);
        CP_COMMIT();

        const uint32_t asb = a_u + s * ASZ;
        const uint32_t bsb = b_u + s * BSZ;
#pragma unroll
        for (int ks = 0; ks < 4; ks++) {
            unsigned a[2][4];
#pragma unroll
            for (int mi = 0; mi < 2; mi++) {
                int row = arow0 + mi * 16;
                int ch  = (ks * 2 + ahc) ^ (row & 7);
                LDSM_X4(a[mi], asb + (uint32_t)(row * 128 + ch * 16));
            }
            unsigned b[4][4];
#pragma unroll
            for (int p = 0; p < 4; p++) {
                int row = brow0 + p * 16;
                int ch  = (ks * 2 + bhc) ^ (row & 7);
                LDSM_X4(b[p], bsb + (uint32_t)(row * 128 + ch * 16));
            }
#pragma unroll
            for (int mi = 0; mi < 2; mi++)
#pragma unroll
                for (int nf = 0; nf < 8; nf++)
                    MMA_TF32(acc[mi][nf], a[mi],
                             b[nf >> 1][(nf & 1) * 2], b[nf >> 1][(nf & 1) * 2 + 1]);
        }
        __syncthreads();
    }
    CP_WAIT0();

    // epilogue: bias (+relu) (+tf32 round), float2 stores
    const int relu = flags & 1, rnd = flags & 2;
    const int g = lane >> 2, t = lane & 3;
#pragma unroll
    for (int mi = 0; mi < 2; mi++) {
        int row = row0 + wm * 32 + mi * 16 + g;
#pragma unroll
        for (int nf = 0; nf < 8; nf++) {
            int col = col0 + wn * 64 + nf * 8 + t * 2;
            float2 bb = *(const float2*)&bias[col];
            float2 v0 = make_float2(acc[mi][nf][0] + bb.x, acc[mi][nf][1] + bb.y);
            float2 v1 = make_float2(acc[mi][nf][2] + bb.x, acc[mi][nf][3] + bb.y);
            if (relu) {
                v0.x = fmaxf(v0.x, 0.f); v0.y = fmaxf(v0.y, 0.f);
                v1.x = fmaxf(v1.x, 0.f); v1.y = fmaxf(v1.y, 0.f);
            }
            if (rnd) {
                v0.x = f2tff(v0.x); v0.y = f2tff(v0.y);
                v1.x = f2tff(v1.x); v1.y = f2tff(v1.y);
            }
            *(float2*)&C[(size_t)row * NC + col]       = v0;
            *(float2*)&C[(size_t)(row + 8) * NC + col] = v1;
        }
    }
}

// ---------------------------------------------------------------------------
// Pre-round x to tf32 (so GEMM needs no cvt in the main loop)
// ---------------------------------------------------------------------------
__global__ void round_x(const float* __restrict__ x, float* __restrict__ xr, int n4)
{
    int i = blockIdx.x * 256 + threadIdx.x;
    if (i >= n4) return;
    float4 v = ((const float4*)x)[i];
    v.x = f2tff(v.x); v.y = f2tff(v.y); v.z = f2tff(v.z); v.w = f2tff(v.w);
    ((float4*)xr)[i] = v;
}

// ---------------------------------------------------------------------------
// Weight packing: transpose to [N][K], tf32-round
// ---------------------------------------------------------------------------
__global__ void pack_T(const float* __restrict__ w, const float* __restrict__ b,
                       int K)
{
    int idx = blockIdx.x * 256 + threadIdx.x;
    int k = idx % K;
    int n = idx / K;
    g_wT[(size_t)n * K + k] = f2tff(w[(size_t)k * 256 + n]);
    if (idx < 256) g_bpack[idx] = b[idx];
}

__global__ void pack4_T(const float* __restrict__ qw, const float* __restrict__ kw,
                        const float* __restrict__ vw, const float* __restrict__ sw,
                        const float* __restrict__ qb, const float* __restrict__ kb,
                        const float* __restrict__ vb, const float* __restrict__ sb)
{
    int idx = blockIdx.x * 256 + threadIdx.x;   // 256*1024
    int k = idx & 255;
    int n = idx >> 8;
    int sel = n >> 8, jj = n & 255;
    const float* w = (sel == 0) ? qw : (sel == 1) ? kw : (sel == 2) ? vw : sw;
    g_wT[(size_t)n * 256 + k] = f2tff(w[(size_t)k * 256 + jj]);
    if (idx < DIM_QKVS) {
        int s2 = idx >> 8, j2 = idx & 255;
        const float* b = (s2 == 0) ? qb : (s2 == 1) ? kb : (s2 == 2) ? vb : sb;
        g_bpack[idx] = b[j2];
    }
}

// ---------------------------------------------------------------------------
// Fused per-frame attention + beta skip + LayerNorm + ReLU
// round_out: tf32-round the stored result (when it feeds the next GEMM)
// ---------------------------------------------------------------------------
__device__ __forceinline__ float warp_sum(float v) {
#pragma unroll
    for (int o = 16; o > 0; o >>= 1) v += __shfl_xor_sync(0xffffffffu, v, o);
    return v;
}

__global__ __launch_bounds__(256)
void attn_ln_kernel(const float* __restrict__ qkvs, const float* __restrict__ bw,
                    const float* __restrict__ ln_g, const float* __restrict__ ln_b,
                    float* __restrict__ out, int round_out)
{
    __shared__ __align__(16) float s_all[4 * DIM_QKVS];
    __shared__ float s_sc[64];
    __shared__ float s_alpha[64];
    __shared__ float s_part[64];

    const int frame = blockIdx.x;
    const int tid = threadIdx.x, lane = tid & 31, wid = tid >> 5;

    const float4* src = (const float4*)(qkvs + (size_t)frame * (4 * DIM_QKVS));
    float4* dst4 = (float4*)s_all;
#pragma unroll
    for (int r = 0; r < 4; r++) dst4[tid + r * 256] = src[tid + r * 256];
    __syncthreads();

    if (tid < 64) {
        int h = tid >> 4, i = (tid >> 2) & 3, j = tid & 3;
        float d = -1e30f;
        if (i != j) {
            const float4* qp = (const float4*)&s_all[i * 1024 + h * 64];
            const float4* kp = (const float4*)&s_all[j * 1024 + 256 + h * 64];
            float acc = 0.f;
#pragma unroll
            for (int c = 0; c < 16; c++) {
                float4 a = qp[c], b = kp[c];
                acc += a.x * b.x + a.y * b.y + a.z * b.z + a.w * b.w;
            }
            d = acc * 0.125f;
        }
        s_sc[tid] = d;
    }
    __syncthreads();

    if (tid < 16) {
        int h = tid >> 2, i = tid & 3;
        int base = h * 16 + i * 4;
        float m = -1e30f;
#pragma unroll
        for (int j = 0; j < 4; j++) if (j != i) m = fmaxf(m, s_sc[base + j]);
        float e[4]; float sum = 0.f;
#pragma unroll
        for (int j = 0; j < 4; j++) {
            e[j] = (j == i) ? 0.f : expf(s_sc[base + j] - m);
            sum += e[j];
        }
        float inv = 1.f / sum;
#pragma unroll
        for (int j = 0; j < 4; j++) s_alpha[base + j] = e[j] * inv;
    }
    __syncthreads();

    const int h = tid >> 6;
    float o[4], xr[4];
#pragma unroll
    for (int i = 0; i < 4; i++) {
        float acc = 0.f;
#pragma unroll
        for (int j = 0; j < 4; j++)
            acc = fmaf(s_alpha[h * 16 + i * 4 + j], s_all[j * 1024 + 512 + tid], acc);
        o[i]  = acc;
        xr[i] = s_all[i * 1024 + 768 + tid];
    }

    const float bw0 = __ldg(&bw[tid]);
    const float bw1 = __ldg(&bw[256 + tid]);
    const float bw2 = __ldg(&bw[512 + tid]);
#pragma unroll
    for (int i = 0; i < 4; i++) {
        float v = warp_sum(o[i] * bw0 + xr[i] * bw1 + (o[i] - xr[i]) * bw2);
        if (lane == 0) s_part[i * 8 + wid] = v;
    }
    __syncthreads();

    float y[4];
#pragma unroll
    for (int i = 0; i < 4; i++) {
        float s = 0.f;
#pragma unroll
        for (int w = 0; w < 8; w++) s += s_part[i * 8 + w];
        float beta = 1.f / (1.f + expf(-s));
        y[i] = beta * xr[i] + (1.f - beta) * o[i];
    }
    __syncthreads();

#pragma unroll
    for (int i = 0; i < 4; i++) {
        float vs = warp_sum(y[i]);
        float vq = warp_sum(y[i] * y[i]);
        if (lane == 0) { s_part[i * 8 + wid] = vs; s_part[32 + i * 8 + wid] = vq; }
    }
    __syncthreads();

    const float g = __ldg(&ln_g[tid]);
    const float b = __ldg(&ln_b[tid]);
    float* dst = out + (size_t)frame * (4 * DIM_F);
#pragma unroll
    for (int i = 0; i < 4; i++) {
        float ssum = 0.f, ssq = 0.f;
#pragma unroll
        for (int w = 0; w < 8; w++) { ssum += s_part[i * 8 + w]; ssq += s_part[32 + i * 8 + w]; }
        float mu  = ssum * (1.f / 256.f);
        float var = ssq * (1.f / 256.f) - mu * mu;
        float inv = rsqrtf(var + 1e-5f);
        float val = fmaxf((y[i] - mu) * inv * g + b, 0.f);
        if (round_out) val = f2tff(val);
        dst[i * 256 + tid] = val;
    }
}

// ---------------------------------------------------------------------------
// Launch sequence
// ---------------------------------------------------------------------------
extern "C" void kernel_launch(void* const* d_in, const int* in_sizes, int n_in,
                              void* d_out, int out_size)
{
    (void)in_sizes; (void)n_in; (void)out_size;
    const float* x     = (const float*)d_in[0];
    const float* emb_w = (const float*)d_in[1];
    const float* emb_b = (const float*)d_in[2];
    const float* q1w = (const float*)d_in[3];  const float* q1b = (const float*)d_in[4];
    const float* k1w = (const float*)d_in[5];  const float* k1b = (const float*)d_in[6];
    const float* v1w = (const float*)d_in[7];  const float* v1b = (const float*)d_in[8];
    const float* s1w = (const float*)d_in[9];  const float* s1b = (const float*)d_in[10];
    const float* b1w = (const float*)d_in[11];
    const float* ln1_g = (const float*)d_in[12]; const float* ln1_b = (const float*)d_in[13];
    const float* q2w = (const float*)d_in[14]; const float* q2b = (const float*)d_in[15];
    const float* k2w = (const float*)d_in[16]; const float* k2b = (const float*)d_in[17];
    const float* v2w = (const float*)d_in[18]; const float* v2b = (const float*)d_in[19];
    const float* s2w = (const float*)d_in[20]; const float* s2b = (const float*)d_in[21];
    const float* b2w = (const float*)d_in[22];
    const float* ln2_g = (const float*)d_in[23]; const float* ln2_b = (const float*)d_in[24];
    float* out = (float*)d_out;

    float *h, *qkvs, *wp, *bp;
    cudaGetSymbolAddress((void**)&h, g_h);
    cudaGetSymbolAddress((void**)&qkvs, g_qkvs);
    cudaGetSymbolAddress((void**)&wp, g_wT);
    cudaGetSymbolAddress((void**)&bp, g_bpack);

    static int smem_set = 0;
    if (!smem_set) {
        cudaFuncSetAttribute(gemm_tf32, cudaFuncAttributeMaxDynamicSharedMemorySize,
                             GEMM_SMEM);
        smem_set = 1;
    }

    // x -> tf32-rounded copy (staged in g_qkvs, free before conv1 GEMM)
    const int n4 = NROWS * DIM_D / 4;
    round_x<<<(n4 + 255) / 256, 256>>>(x, qkvs, n4);

    // Embedding: h = relu(x @ emb_w + emb_b), tf32-rounded for next GEMM
    pack_T<<<(DIM_D * DIM_F) / 256, 256>>>(emb_w, emb_b, DIM_D);
    gemm_tf32<<<dim3(DIM_F / 256, NROWS / 128), 512, GEMM_SMEM>>>(
        qkvs, wp, bp, h, DIM_D, DIM_F, 1 | 2);

    // --- Conv 1 ---
    pack4_T<<<(DIM_F * DIM_QKVS) / 256, 256>>>(q1w, k1w, v1w, s1w, q1b, k1b, v1b, s1b);
    gemm_tf32<<<dim3(DIM_QKVS / 256, NROWS / 128), 512, GEMM_SMEM>>>(
        h, wp, bp, qkvs, DIM_F, DIM_QKVS, 0);
    attn_ln_kernel<<<NFRAMES, 256>>>(qkvs, b1w, ln1_g, ln1_b, h, 1);

    // --- Conv 2 ---
    pack4_T<<<(DIM_F * DIM_QKVS) / 256, 256>>>(q2w, k2w, v2w, s2w, q2b, k2b, v2b, s2b);
    gemm_tf32<<<dim3(DIM_QKVS / 256, NROWS / 128), 512, GEMM_SMEM>>>(
        h, wp, bp, qkvs, DIM_F, DIM_QKVS, 0);
    attn_ln_kernel<<<NFRAMES, 256>>>(qkvs, b2w, ln2_g, ln2_b, out, 0);
}

// round 5
// speedup vs baseline: 4.1085x; 1.3706x over previous
#include <cuda_runtime.h>
#include <cuda_fp16.h>
#include <cstdint>
#include <math.h>

// ---------------------------------------------------------------------------
// B=16, T=2048, M=4, D=128, F=256, H=4, C=64
// Nf = 32768 frames, Nrows = 131072
// Toolchain targets sm_100 (no 'a') -> legacy mma.sync path; fp16 mma k16
// doubles tensor throughput vs tf32 k8 at the SAME 10-bit mantissa.
// ---------------------------------------------------------------------------
#define NFRAMES   32768
#define NROWS     131072
#define DIM_D     128
#define DIM_F     256
#define DIM_QKVS  1024

// Scratch (device globals: allocation-free, graph-safe)
__device__ __half g_x[NROWS * DIM_D];          // 32 MB: x in fp16
__device__ __half g_h[NROWS * DIM_F];          // 64 MB: hidden activations
__device__ __half g_qkvs[NROWS * DIM_QKVS];    // 256 MB: fused q|k|v|s
__device__ __half g_wT[DIM_QKVS * DIM_F];      // packed transposed weights [NC][K]
__device__ float  g_bpack[DIM_QKVS];           // packed bias (fp32)

__device__ __forceinline__ uint32_t swz(uint32_t off) {   // 128B-row XOR swizzle
    return off ^ ((off >> 3) & 0x70);
}

#define CP_ASYNC16(dst, src) \
    asm volatile("cp.async.cg.shared.global [%0], [%1], 16;" :: "r"(dst), "l"(src))
#define CP_COMMIT() asm volatile("cp.async.commit_group;")
#define CP_WAIT1()  asm volatile("cp.async.wait_group 1;" ::: "memory")
#define CP_WAIT0()  asm volatile("cp.async.wait_group 0;" ::: "memory")

#define LDSM_X4(r, addr)                                                        \
    asm volatile("ldmatrix.sync.aligned.m8n8.x4.shared.b16 {%0,%1,%2,%3}, [%4];" \
                 : "=r"((r)[0]), "=r"((r)[1]), "=r"((r)[2]), "=r"((r)[3])        \
                 : "r"(addr))

#define MMA_F16(c, a, b0v, b1v)                                                 \
    asm volatile("mma.sync.aligned.m16n8k16.row.col.f32.f16.f16.f32 "           \
                 "{%0,%1,%2,%3},{%4,%5,%6,%7},{%8,%9},{%0,%1,%2,%3};"           \
                 : "+f"((c)[0]), "+f"((c)[1]), "+f"((c)[2]), "+f"((c)[3])        \
                 : "r"((a)[0]), "r"((a)[1]), "r"((a)[2]), "r"((a)[3]),           \
                   "r"(b0v), "r"(b1v))

// ---------------------------------------------------------------------------
// fp16 mma.sync GEMM, cp.async 3-stage pipeline.
// C[NROWS x NC] (half) = act(A @ Wt^T + bias);  A half [rows x K], Wt half
// [NC x K]. BM=128, BN=256, BK=64 halves (128B rows), 512 threads (16 warps
// 4x4, 32x64 warp tile). relu flag applies max(0,.) before store.
// ---------------------------------------------------------------------------
#define STAGES 3
#define ASZ (128 * 128)      // 16 KB (128 rows x 128 B)
#define BSZ (256 * 128)      // 32 KB
#define GEMM_SMEM (STAGES * (ASZ + BSZ))   // 147456 B

__global__ __launch_bounds__(512, 1)
void gemm_f16(const __half* __restrict__ A, const __half* __restrict__ Wt,
              const float* __restrict__ bias, __half* __restrict__ C,
              int K, int NC, int relu)
{
    extern __shared__ __align__(128) char smem[];
    const uint32_t smem_u = (uint32_t)__cvta_generic_to_shared(smem);
    const uint32_t a_u = smem_u;
    const uint32_t b_u = smem_u + STAGES * ASZ;

    const int tid  = threadIdx.x;
    const int lane = tid & 31;
    const int wid  = tid >> 5;
    const int wm   = wid & 3;      // row group (32 rows)
    const int wn   = wid >> 2;     // col group (64 cols)
    const int row0 = blockIdx.y * 128;
    const int col0 = blockIdx.x * 256;

    float acc[2][8][4];
#pragma unroll
    for (int mi = 0; mi < 2; mi++)
#pragma unroll
        for (int nf = 0; nf < 8; nf++)
#pragma unroll
            for (int c = 0; c < 4; c++) acc[mi][nf][c] = 0.f;

    const int nch = K >> 6;   // 64 halves per chunk

    // staging: A 1024 16B-chunks (2/thread), B 2048 (4/thread); 8 halves/chunk
    const int ar[2] = { tid >> 3, (tid + 512) >> 3 };
    const int ac    = tid & 7;
    const int br[4] = { tid >> 3, (tid + 512) >> 3, (tid + 1024) >> 3, (tid + 1536) >> 3 };

    auto stage = [&](int s, int c) {
        const int k0 = c * 64;
        const uint32_t abase = a_u + s * ASZ;
        const uint32_t bbase = b_u + s * BSZ;
#pragma unroll
        for (int t = 0; t < 2; t++) {
            const __half* src = A + (size_t)(row0 + ar[t]) * K + k0 + ac * 8;
            CP_ASYNC16(abase + swz(ar[t] * 128 + ac * 16), src);
        }
#pragma unroll
        for (int t = 0; t < 4; t++) {
            const __half* src = Wt + (size_t)(col0 + br[t]) * K + k0 + ac * 8;
            CP_ASYNC16(bbase + swz(br[t] * 128 + ac * 16), src);
        }
    };

    stage(0, 0); CP_COMMIT();
    if (nch > 1) { stage(1, 1); CP_COMMIT(); }
    else         { CP_COMMIT(); }   // keep group count consistent

    // ldmatrix lane bases
    const int arow0 = wm * 32 + (lane & 15);        // + mi*16
    const int ahc   = lane >> 4;                    // k-chunk select (0/1)
    const int brow0 = wn * 64 + (lane & 7) + ((lane >> 4) & 1) * 8;   // + p*16
    const int bhc   = (lane >> 3) & 1;

    for (int c = 0; c < nch; c++) {
        CP_WAIT1();
        __syncthreads();
        const int s = c % STAGES;
        if (c + 2 < nch) stage((c + 2) % STAGES, c + 2);
        CP_COMMIT();

        const uint32_t asb = a_u + s * ASZ;
        const uint32_t bsb = b_u + s * BSZ;
#pragma unroll
        for (int ks = 0; ks < 4; ks++) {          // 4 x k16 per 64-half chunk
            unsigned a[2][4];
#pragma unroll
            for (int mi = 0; mi < 2; mi++) {
                int row = arow0 + mi * 16;
                int ch  = (ks * 2 + ahc) ^ (row & 7);
                LDSM_X4(a[mi], asb + (uint32_t)(row * 128 + ch * 16));
            }
            unsigned b[4][4];  // [p]: {b0 n0-8, b1 n0-8, b0 n8-16, b1 n8-16}
#pragma unroll
            for (int p = 0; p < 4; p++) {
                int row = brow0 + p * 16;
                int ch  = (ks * 2 + bhc) ^ (row & 7);
                LDSM_X4(b[p], bsb + (uint32_t)(row * 128 + ch * 16));
            }
#pragma unroll
            for (int mi = 0; mi < 2; mi++)
#pragma unroll
                for (int nf = 0; nf < 8; nf++)
                    MMA_F16(acc[mi][nf], a[mi],
                            b[nf >> 1][(nf & 1) * 2], b[nf >> 1][(nf & 1) * 2 + 1]);
        }
        __syncthreads();
    }
    CP_WAIT0();

    // epilogue: bias (+relu), half2 stores
    const int g = lane >> 2, t = lane & 3;
#pragma unroll
    for (int mi = 0; mi < 2; mi++) {
        int row = row0 + wm * 32 + mi * 16 + g;
#pragma unroll
        for (int nf = 0; nf < 8; nf++) {
            int col = col0 + wn * 64 + nf * 8 + t * 2;
            float2 bb = *(const float2*)&bias[col];
            float2 v0 = make_float2(acc[mi][nf][0] + bb.x, acc[mi][nf][1] + bb.y);
            float2 v1 = make_float2(acc[mi][nf][2] + bb.x, acc[mi][nf][3] + bb.y);
            if (relu) {
                v0.x = fmaxf(v0.x, 0.f); v0.y = fmaxf(v0.y, 0.f);
                v1.x = fmaxf(v1.x, 0.f); v1.y = fmaxf(v1.y, 0.f);
            }
            *(__half2*)&C[(size_t)row * NC + col]       = __floats2half2_rn(v0.x, v0.y);
            *(__half2*)&C[(size_t)(row + 8) * NC + col] = __floats2half2_rn(v1.x, v1.y);
        }
    }
}

// ---------------------------------------------------------------------------
// x fp32 -> fp16
// ---------------------------------------------------------------------------
__global__ void convert_x(const float* __restrict__ x, __half* __restrict__ xh, int n4)
{
    int i = blockIdx.x * 256 + threadIdx.x;
    if (i >= n4) return;
    float4 v = ((const float4*)x)[i];
    __half2 h0 = __floats2half2_rn(v.x, v.y);
    __half2 h1 = __floats2half2_rn(v.z, v.w);
    ((__half2*)xh)[2 * i]     = h0;
    ((__half2*)xh)[2 * i + 1] = h1;
}

// ---------------------------------------------------------------------------
// Weight packing: transpose to [N][K], fp16
// ---------------------------------------------------------------------------
__global__ void pack_T(const float* __restrict__ w, const float* __restrict__ b,
                       int K)
{
    int idx = blockIdx.x * 256 + threadIdx.x;
    int k = idx % K;
    int n = idx / K;
    g_wT[(size_t)n * K + k] = __float2half(w[(size_t)k * 256 + n]);
    if (idx < 256) g_bpack[idx] = b[idx];
}

__global__ void pack4_T(const float* __restrict__ qw, const float* __restrict__ kw,
                        const float* __restrict__ vw, const float* __restrict__ sw,
                        const float* __restrict__ qb, const float* __restrict__ kb,
                        const float* __restrict__ vb, const float* __restrict__ sb)
{
    int idx = blockIdx.x * 256 + threadIdx.x;   // 256*1024
    int k = idx & 255;
    int n = idx >> 8;
    int sel = n >> 8, jj = n & 255;
    const float* w = (sel == 0) ? qw : (sel == 1) ? kw : (sel == 2) ? vw : sw;
    g_wT[(size_t)n * 256 + k] = __float2half(w[(size_t)k * 256 + jj]);
    if (idx < DIM_QKVS) {
        int s2 = idx >> 8, j2 = idx & 255;
        const float* b = (s2 == 0) ? qb : (s2 == 1) ? kb : (s2 == 2) ? vb : sb;
        g_bpack[idx] = b[j2];
    }
}

// ---------------------------------------------------------------------------
// Fused per-frame attention + beta skip + LayerNorm + ReLU.
// Input qkvs fp16; all math fp32; output half (mid) or float (final).
// ---------------------------------------------------------------------------
__device__ __forceinline__ float warp_sum(float v) {
#pragma unroll
    for (int o = 16; o > 0; o >>= 1) v += __shfl_xor_sync(0xffffffffu, v, o);
    return v;
}

__device__ __forceinline__ void store_act(__half* p, float v) { *p = __float2half(v); }
__device__ __forceinline__ void store_act(float* p, float v)  { *p = v; }

template <typename OutT>
__global__ __launch_bounds__(256)
void attn_ln_kernel(const __half* __restrict__ qkvs, const float* __restrict__ bw,
                    const float* __restrict__ ln_g, const float* __restrict__ ln_b,
                    OutT* __restrict__ out)
{
    __shared__ __align__(16) float s_all[4 * DIM_QKVS];   // 16 KB fp32
    __shared__ float s_sc[64];
    __shared__ float s_alpha[64];
    __shared__ float s_part[64];

    const int frame = blockIdx.x;
    const int tid = threadIdx.x, lane = tid & 31, wid = tid >> 5;

    const __half2* src = (const __half2*)(qkvs + (size_t)frame * (4 * DIM_QKVS));
#pragma unroll
    for (int r = 0; r < 8; r++) {
        int i = tid + r * 256;                 // half2 index, 2048 total
        float2 f = __half22float2(src[i]);
        *(float2*)&s_all[2 * i] = f;
    }
    __syncthreads();

    if (tid < 64) {
        int h = tid >> 4, i = (tid >> 2) & 3, j = tid & 3;
        float d = -1e30f;
        if (i != j) {
            const float4* qp = (const float4*)&s_all[i * 1024 + h * 64];
            const float4* kp = (const float4*)&s_all[j * 1024 + 256 + h * 64];
            float acc = 0.f;
#pragma unroll
            for (int c = 0; c < 16; c++) {
                float4 a = qp[c], b = kp[c];
                acc += a.x * b.x + a.y * b.y + a.z * b.z + a.w * b.w;
            }
            d = acc * 0.125f;
        }
        s_sc[tid] = d;
    }
    __syncthreads();

    if (tid < 16) {
        int h = tid >> 2, i = tid & 3;
        int base = h * 16 + i * 4;
        float m = -1e30f;
#pragma unroll
        for (int j = 0; j < 4; j++) if (j != i) m = fmaxf(m, s_sc[base + j]);
        float e[4]; float sum = 0.f;
#pragma unroll
        for (int j = 0; j < 4; j++) {
            e[j] = (j == i) ? 0.f : expf(s_sc[base + j] - m);
            sum += e[j];
        }
        float inv = 1.f / sum;
#pragma unroll
        for (int j = 0; j < 4; j++) s_alpha[base + j] = e[j] * inv;
    }
    __syncthreads();

    const int h = tid >> 6;
    float o[4], xr[4];
#pragma unroll
    for (int i = 0; i < 4; i++) {
        float acc = 0.f;
#pragma unroll
        for (int j = 0; j < 4; j++)
            acc = fmaf(s_alpha[h * 16 + i * 4 + j], s_all[j * 1024 + 512 + tid], acc);
        o[i]  = acc;
        xr[i] = s_all[i * 1024 + 768 + tid];
    }

    const float bw0 = __ldg(&bw[tid]);
    const float bw1 = __ldg(&bw[256 + tid]);
    const float bw2 = __ldg(&bw[512 + tid]);
#pragma unroll
    for (int i = 0; i < 4; i++) {
        float v = warp_sum(o[i] * bw0 + xr[i] * bw1 + (o[i] - xr[i]) * bw2);
        if (lane == 0) s_part[i * 8 + wid] = v;
    }
    __syncthreads();

    float y[4];
#pragma unroll
    for (int i = 0; i < 4; i++) {
        float s = 0.f;
#pragma unroll
        for (int w = 0; w < 8; w++) s += s_part[i * 8 + w];
        float beta = 1.f / (1.f + expf(-s));
        y[i] = beta * xr[i] + (1.f - beta) * o[i];
    }
    __syncthreads();

#pragma unroll
    for (int i = 0; i < 4; i++) {
        float vs = warp_sum(y[i]);
        float vq = warp_sum(y[i] * y[i]);
        if (lane == 0) { s_part[i * 8 + wid] = vs; s_part[32 + i * 8 + wid] = vq; }
    }
    __syncthreads();

    const float g = __ldg(&ln_g[tid]);
    const float b = __ldg(&ln_b[tid]);
    OutT* dst = out + (size_t)frame * (4 * DIM_F);
#pragma unroll
    for (int i = 0; i < 4; i++) {
        float ssum = 0.f, ssq = 0.f;
#pragma unroll
        for (int w = 0; w < 8; w++) { ssum += s_part[i * 8 + w]; ssq += s_part[32 + i * 8 + w]; }
        float mu  = ssum * (1.f / 256.f);
        float var = ssq * (1.f / 256.f) - mu * mu;
        float inv = rsqrtf(var + 1e-5f);
        float val = fmaxf((y[i] - mu) * inv * g + b, 0.f);
        store_act(&dst[i * 256 + tid], val);
    }
}

// ---------------------------------------------------------------------------
// Launch sequence
// ---------------------------------------------------------------------------
extern "C" void kernel_launch(void* const* d_in, const int* in_sizes, int n_in,
                              void* d_out, int out_size)
{
    (void)in_sizes; (void)n_in; (void)out_size;
    const float* x     = (const float*)d_in[0];
    const float* emb_w = (const float*)d_in[1];
    const float* emb_b = (const float*)d_in[2];
    const float* q1w = (const float*)d_in[3];  const float* q1b = (const float*)d_in[4];
    const float* k1w = (const float*)d_in[5];  const float* k1b = (const float*)d_in[6];
    const float* v1w = (const float*)d_in[7];  const float* v1b = (const float*)d_in[8];
    const float* s1w = (const float*)d_in[9];  const float* s1b = (const float*)d_in[10];
    const float* b1w = (const float*)d_in[11];
    const float* ln1_g = (const float*)d_in[12]; const float* ln1_b = (const float*)d_in[13];
    const float* q2w = (const float*)d_in[14]; const float* q2b = (const float*)d_in[15];
    const float* k2w = (const float*)d_in[16]; const float* k2b = (const float*)d_in[17];
    const float* v2w = (const float*)d_in[18]; const float* v2b = (const float*)d_in[19];
    const float* s2w = (const float*)d_in[20]; const float* s2b = (const float*)d_in[21];
    const float* b2w = (const float*)d_in[22];
    const float* ln2_g = (const float*)d_in[23]; const float* ln2_b = (const float*)d_in[24];
    float* out = (float*)d_out;

    __half *xh, *h, *qkvs, *wp;
    float* bp;
    cudaGetSymbolAddress((void**)&xh, g_x);
    cudaGetSymbolAddress((void**)&h, g_h);
    cudaGetSymbolAddress((void**)&qkvs, g_qkvs);
    cudaGetSymbolAddress((void**)&wp, g_wT);
    cudaGetSymbolAddress((void**)&bp, g_bpack);

    static int smem_set = 0;
    if (!smem_set) {
        cudaFuncSetAttribute(gemm_f16, cudaFuncAttributeMaxDynamicSharedMemorySize,
                             GEMM_SMEM);
        smem_set = 1;
    }

    // x -> fp16
    const int n4 = NROWS * DIM_D / 4;
    convert_x<<<(n4 + 255) / 256, 256>>>(x, xh, n4);

    // Embedding: h = relu(x @ emb_w + emb_b)
    pack_T<<<(DIM_D * DIM_F) / 256, 256>>>(emb_w, emb_b, DIM_D);
    gemm_f16<<<dim3(DIM_F / 256, NROWS / 128), 512, GEMM_SMEM>>>(
        xh, wp, bp, h, DIM_D, DIM_F, 1);

    // --- Conv 1 ---
    pack4_T<<<(DIM_F * DIM_QKVS) / 256, 256>>>(q1w, k1w, v1w, s1w, q1b, k1b, v1b, s1b);
    gemm_f16<<<dim3(DIM_QKVS / 256, NROWS / 128), 512, GEMM_SMEM>>>(
        h, wp, bp, qkvs, DIM_F, DIM_QKVS, 0);
    attn_ln_kernel<__half><<<NFRAMES, 256>>>(qkvs, b1w, ln1_g, ln1_b, h);

    // --- Conv 2 ---
    pack4_T<<<(DIM_F * DIM_QKVS) / 256, 256>>>(q2w, k2w, v2w, s2w, q2b, k2b, v2b, s2b);
    gemm_f16<<<dim3(DIM_QKVS / 256, NROWS / 128), 512, GEMM_SMEM>>>(
        h, wp, bp, qkvs, DIM_F, DIM_QKVS, 0);
    attn_ln_kernel<float><<<NFRAMES, 256>>>(qkvs, b2w, ln2_g, ln2_b, out);
}